// round 16
// baseline (speedup 1.0000x reference)
#include <cuda_runtime.h>
#include <cuda_bf16.h>
#include <cstdint>

// Sliding-window causal attention, fp32, no 1/sqrt(d) scaling.
// B=2, H=12, S=2048, D=64, W=256. Mask analytic: j in (i-W, i].
// v16: byte-identical v7 structure (best measured: 47.4us). Single change:
//      Q pre-scaled by log2e at load (before hi/lo split), exp -> ex2.approx.
//      Removes 32 FMULs/thread-chunk from the serial exp chain; nothing else
//      (ordering, smem, regs pattern, barriers) is touched.

#define DH   64
#define WIN  256
#define SEQ  2048
#define BM   64
#define BN   32
#define NT   128
#define KST  72                       // row stride in halves
#define BUFB (BN * KST * 2)           // bytes per array per buffer (4608)

__device__ __forceinline__ uint32_t packbf(float hi, float lo) {
    uint32_t d; asm("cvt.rn.bf16x2.f32 %0, %1, %2;" : "=r"(d) : "f"(hi), "f"(lo));
    return d;
}
__device__ __forceinline__ float hi_f(uint32_t r) { return __uint_as_float(r & 0xffff0000u); }
__device__ __forceinline__ float lo_f(uint32_t r) { return __uint_as_float(r << 16); }
__device__ __forceinline__ float ex2f(float x) {
    float r; asm("ex2.approx.f32 %0, %1;" : "=f"(r) : "f"(x)); return r;
}

__device__ __forceinline__ void mma16816(float* c,
    uint32_t a0, uint32_t a1, uint32_t a2, uint32_t a3,
    uint32_t b0, uint32_t b1)
{
    asm("mma.sync.aligned.m16n8k16.row.col.f32.bf16.bf16.f32 "
        "{%0,%1,%2,%3}, {%4,%5,%6,%7}, {%8,%9}, {%0,%1,%2,%3};"
        : "+f"(c[0]), "+f"(c[1]), "+f"(c[2]), "+f"(c[3])
        : "r"(a0), "r"(a1), "r"(a2), "r"(a3), "r"(b0), "r"(b1));
}
__device__ __forceinline__ void ldsm4(uint32_t* r, uint32_t a) {
    asm volatile("ldmatrix.sync.aligned.m8n8.x4.shared.b16 {%0,%1,%2,%3}, [%4];"
        : "=r"(r[0]), "=r"(r[1]), "=r"(r[2]), "=r"(r[3]) : "r"(a));
}
__device__ __forceinline__ void ldsm4t(uint32_t* r, uint32_t a) {
    asm volatile("ldmatrix.sync.aligned.m8n8.x4.trans.shared.b16 {%0,%1,%2,%3}, [%4];"
        : "=r"(r[0]), "=r"(r[1]), "=r"(r[2]), "=r"(r[3]) : "r"(a));
}

__global__ __launch_bounds__(NT, 3) void swa_mma16(
    const float* __restrict__ q,
    const float* __restrict__ k,
    const float* __restrict__ v,
    float* __restrict__ out)
{
    __shared__ __align__(16) uint16_t Kh[2][BN * KST];
    __shared__ __align__(16) uint16_t Klo[2][BN * KST];
    __shared__ __align__(16) uint16_t Vh[2][BN * KST];
    __shared__ __align__(16) uint16_t Vlo[2][BN * KST];

    const int t    = threadIdx.x;
    const int lane = t & 31;
    const int wid  = t >> 5;
    const int g    = lane >> 2;
    const int tg   = lane & 3;
    const int i0   = blockIdx.x * BM;
    const int w0   = i0 + wid * 16;
    const int rowA = w0 + g;
    const int rowB = rowA + 8;
    const size_t base = (size_t)blockIdx.y * SEQ * DH;

    // chunk-invariant ldmatrix lane bases (buffer 0; add buf*BUFB)
    const uint32_t khB = (uint32_t)__cvta_generic_to_shared(&Kh[0][0])
                       + ((lane & 7) * KST + (lane >> 3) * 8) * 2;
    const uint32_t klB = (uint32_t)__cvta_generic_to_shared(&Klo[0][0])
                       + ((lane & 7) * KST + (lane >> 3) * 8) * 2;
    const uint32_t vhB = (uint32_t)__cvta_generic_to_shared(&Vh[0][0])
                       + (((lane & 7) + ((lane >> 3) & 1) * 8) * KST) * 2
                       + (lane >> 4) * 16;
    const uint32_t vlB = (uint32_t)__cvta_generic_to_shared(&Vlo[0][0])
                       + (((lane & 7) + ((lane >> 3) & 1) * 8) * KST) * 2
                       + (lane >> 4) * 16;

    // loader destination indices
    int ldj[4], lddq[4];
    #pragma unroll
    for (int i = 0; i < 4; i++) {
        const int gi = t + i * NT;
        ldj[i]  = gi >> 4;
        lddq[i] = (gi & 15) * 4;
    }

    // ---- Q fragments (hi/lo), loaded once, pre-scaled by log2e ----
    const float L2E = 1.4426950408889634f;
    uint32_t qh[4][4], ql[4][4];
    {
        const float* qp = q + base;
        #pragma unroll
        for (int kd = 0; kd < 4; kd++) {
            const int d0 = kd * 16 + tg * 2;
            const float xA0 = qp[(size_t)rowA * DH + d0]     * L2E;
            const float xA1 = qp[(size_t)rowA * DH + d0 + 1] * L2E;
            const float xB0 = qp[(size_t)rowB * DH + d0]     * L2E;
            const float xB1 = qp[(size_t)rowB * DH + d0 + 1] * L2E;
            const float yA0 = qp[(size_t)rowA * DH + d0 + 8] * L2E;
            const float yA1 = qp[(size_t)rowA * DH + d0 + 9] * L2E;
            const float yB0 = qp[(size_t)rowB * DH + d0 + 8] * L2E;
            const float yB1 = qp[(size_t)rowB * DH + d0 + 9] * L2E;
            qh[kd][0] = packbf(xA1, xA0);
            qh[kd][1] = packbf(xB1, xB0);
            qh[kd][2] = packbf(yA1, yA0);
            qh[kd][3] = packbf(yB1, yB0);
            ql[kd][0] = packbf(xA1 - hi_f(qh[kd][0]), xA0 - lo_f(qh[kd][0]));
            ql[kd][1] = packbf(xB1 - hi_f(qh[kd][1]), xB0 - lo_f(qh[kd][1]));
            ql[kd][2] = packbf(yA1 - hi_f(qh[kd][2]), yA0 - lo_f(qh[kd][2]));
            ql[kd][3] = packbf(yB1 - hi_f(qh[kd][3]), yB0 - lo_f(qh[kd][3]));
        }
    }

    float o[8][4];
    #pragma unroll
    for (int m = 0; m < 8; m++) { o[m][0]=0.f; o[m][1]=0.f; o[m][2]=0.f; o[m][3]=0.f; }
    float lsum0 = 0.f, lsum1 = 0.f;

    int js = i0 - WIN + 1;
    if (js < 0) js = 0;
    js &= ~(BN - 1);
    const int nch = (i0 + BM - js) / BN;

    float4 kreg[4], vreg[4];

    auto stschunk = [&](int b) {
        #pragma unroll
        for (int i = 0; i < 4; i++) {
            const int j = ldj[i], dq = lddq[i];
            const float4 kv = kreg[i];
            uint32_t h01 = packbf(kv.y, kv.x);
            uint32_t h23 = packbf(kv.w, kv.z);
            *(uint2*)&Kh[b][j * KST + dq] = make_uint2(h01, h23);
            *(uint2*)&Klo[b][j * KST + dq] = make_uint2(
                packbf(kv.y - hi_f(h01), kv.x - lo_f(h01)),
                packbf(kv.w - hi_f(h23), kv.z - lo_f(h23)));
            const float4 vv = vreg[i];
            h01 = packbf(vv.y, vv.x);
            h23 = packbf(vv.w, vv.z);
            *(uint2*)&Vh[b][j * KST + dq] = make_uint2(h01, h23);
            *(uint2*)&Vlo[b][j * KST + dq] = make_uint2(
                packbf(vv.y - hi_f(h01), vv.x - lo_f(h01)),
                packbf(vv.w - hi_f(h23), vv.z - lo_f(h23)));
        }
    };
    auto ldgchunk = [&](int c) {
        const int j0 = js + c * BN;
        const float4* kp = (const float4*)(k + base + (size_t)j0 * DH);
        const float4* vp = (const float4*)(v + base + (size_t)j0 * DH);
        #pragma unroll
        for (int i = 0; i < 4; i++) {
            kreg[i] = kp[t + i * NT];
            vreg[i] = vp[t + i * NT];
        }
    };

    // prologue: chunk0 -> buf0; prefetch chunk1
    ldgchunk(0);
    stschunk(0);
    ldgchunk(1);
    __syncthreads();

    for (int c = 0; c < nch; c++) {
        const int buf = c & 1;
        const int j0  = js + c * BN;
        const uint32_t bo = (uint32_t)buf * BUFB;

        // ---- compute from buf ----
        if (j0 <= w0 + 15 && j0 + BN - 1 >= w0 - WIN + 1) {
            float s[4][4];
            #pragma unroll
            for (int nt = 0; nt < 4; nt++) { s[nt][0]=0.f; s[nt][1]=0.f; s[nt][2]=0.f; s[nt][3]=0.f; }

            #pragma unroll
            for (int kd2 = 0; kd2 < 2; kd2++) {
                #pragma unroll
                for (int nt = 0; nt < 4; nt++) {
                    uint32_t bh[4], bl[4];
                    const uint32_t off = bo + (uint32_t)(nt * 8 * KST * 2 + kd2 * 64);
                    ldsm4(bh, khB + off);
                    ldsm4(bl, klB + off);
                    const int k0 = 2 * kd2, k1 = 2 * kd2 + 1;
                    mma16816(s[nt], qh[k0][0], qh[k0][1], qh[k0][2], qh[k0][3], bh[0], bh[1]);
                    mma16816(s[nt], qh[k1][0], qh[k1][1], qh[k1][2], qh[k1][3], bh[2], bh[3]);
                    mma16816(s[nt], qh[k0][0], qh[k0][1], qh[k0][2], qh[k0][3], bl[0], bl[1]);
                    mma16816(s[nt], qh[k1][0], qh[k1][1], qh[k1][2], qh[k1][3], bl[2], bl[3]);
                    mma16816(s[nt], ql[k0][0], ql[k0][1], ql[k0][2], ql[k0][3], bh[0], bh[1]);
                    mma16816(s[nt], ql[k1][0], ql[k1][1], ql[k1][2], ql[k1][3], bh[2], bh[3]);
                }
            }

            #pragma unroll
            for (int nt = 0; nt < 4; nt++) {
                const int jc = j0 + nt * 8 + tg * 2;
                const float p00 = ((unsigned)(rowA - jc)       < (unsigned)WIN) ? ex2f(s[nt][0]) : 0.f;
                const float p01 = ((unsigned)(rowA - (jc + 1)) < (unsigned)WIN) ? ex2f(s[nt][1]) : 0.f;
                const float p10 = ((unsigned)(rowB - jc)       < (unsigned)WIN) ? ex2f(s[nt][2]) : 0.f;
                const float p11 = ((unsigned)(rowB - (jc + 1)) < (unsigned)WIN) ? ex2f(s[nt][3]) : 0.f;
                lsum0 += p00 + p01;
                lsum1 += p10 + p11;
                s[nt][0] = p00; s[nt][1] = p01; s[nt][2] = p10; s[nt][3] = p11;
            }

            uint32_t aH[2][4], aL[2][4];
            #pragma unroll
            for (int ks = 0; ks < 2; ks++) {
                const float* pa = s[2 * ks];
                const float* pb = s[2 * ks + 1];
                aH[ks][0] = packbf(pa[1], pa[0]);
                aH[ks][1] = packbf(pa[3], pa[2]);
                aH[ks][2] = packbf(pb[1], pb[0]);
                aH[ks][3] = packbf(pb[3], pb[2]);
                aL[ks][0] = packbf(pa[1] - hi_f(aH[ks][0]), pa[0] - lo_f(aH[ks][0]));
                aL[ks][1] = packbf(pa[3] - hi_f(aH[ks][1]), pa[2] - lo_f(aH[ks][1]));
                aL[ks][2] = packbf(pb[1] - hi_f(aH[ks][2]), pb[0] - lo_f(aH[ks][2]));
                aL[ks][3] = packbf(pb[3] - hi_f(aH[ks][3]), pb[2] - lo_f(aH[ks][3]));
            }

            #pragma unroll
            for (int ks = 0; ks < 2; ks++) {
                #pragma unroll
                for (int mt2 = 0; mt2 < 4; mt2++) {
                    uint32_t bh[4], bl[4];
                    const uint32_t off = bo + (uint32_t)(ks * 16 * KST * 2 + mt2 * 32);
                    ldsm4t(bh, vhB + off);
                    ldsm4t(bl, vlB + off);
                    const int m0 = 2 * mt2, m1 = 2 * mt2 + 1;
                    mma16816(o[m0], aH[ks][0], aH[ks][1], aH[ks][2], aH[ks][3], bh[0], bh[1]);
                    mma16816(o[m1], aH[ks][0], aH[ks][1], aH[ks][2], aH[ks][3], bh[2], bh[3]);
                    mma16816(o[m0], aH[ks][0], aH[ks][1], aH[ks][2], aH[ks][3], bl[0], bl[1]);
                    mma16816(o[m1], aH[ks][0], aH[ks][1], aH[ks][2], aH[ks][3], bl[2], bl[3]);
                    mma16816(o[m0], aL[ks][0], aL[ks][1], aL[ks][2], aL[ks][3], bh[0], bh[1]);
                    mma16816(o[m1], aL[ks][0], aL[ks][1], aL[ks][2], aL[ks][3], bh[2], bh[3]);
                }
            }
        }

        // ---- publish next chunk; prefetch chunk c+2 ----
        if (c + 1 < nch) {
            stschunk((c + 1) & 1);
            if (c + 2 < nch) ldgchunk(c + 2);
        }
        __syncthreads();
    }

    // ---- finalize ----
    lsum0 += __shfl_xor_sync(0xffffffffu, lsum0, 1);
    lsum0 += __shfl_xor_sync(0xffffffffu, lsum0, 2);
    lsum1 += __shfl_xor_sync(0xffffffffu, lsum1, 1);
    lsum1 += __shfl_xor_sync(0xffffffffu, lsum1, 2);
    const float ia = 1.f / lsum0;
    const float ib = 1.f / lsum1;

    float* op = out + base;
    #pragma unroll
    for (int mt = 0; mt < 8; mt++) {
        const int d0 = mt * 8 + tg * 2;
        *(float2*)&op[(size_t)rowA * DH + d0] = make_float2(o[mt][0] * ia, o[mt][1] * ia);
        *(float2*)&op[(size_t)rowB * DH + d0] = make_float2(o[mt][2] * ib, o[mt][3] * ib);
    }
}

extern "C" void kernel_launch(void* const* d_in, const int* in_sizes, int n_in,
                              void* d_out, int out_size)
{
    const float* q = (const float*)d_in[0];
    const float* k = (const float*)d_in[1];
    const float* v = (const float*)d_in[2];
    // d_in[3] = mask (analytic, unused)
    float* out = (float*)d_out;

    dim3 grid(SEQ / BM, 2 * 12);   // 32 x 24 = 768 CTAs
    dim3 block(NT);
    swa_mma16<<<grid, block>>>(q, k, v, out);
}

// round 17
// speedup vs baseline: 1.0233x; 1.0233x over previous
#include <cuda_runtime.h>
#include <cuda_bf16.h>
#include <cstdint>

// Sliding-window causal attention, fp32, no 1/sqrt(d) scaling.
// B=2, H=12, S=2048, D=64, W=256. Mask analytic: j in (i-W, i].
// v17: v7 math/staging verbatim; ONLY change: 4-stage smem ring with
//      __syncthreads every OTHER chunk (barrier count halved, warps may
//      drift 64 keys, prefetch depth 3). Dynamic smem 72 KB, 3 CTAs/SM.

#define DH   64
#define WIN  256
#define SEQ  2048
#define BM   64
#define BN   32
#define NT   128
#define KST  72                        // row stride in halves (144 B)
#define ARR  4608                      // bytes per array (32*144)
#define STG  (4 * ARR)                 // one ring stage: Kh|Kl|Vh|Vl = 18432
#define SMEM_TOTAL (4 * STG)           // 73728

__device__ __forceinline__ uint32_t smem_u32(const void* p) {
    uint32_t a;
    asm("{ .reg .u64 t; cvta.to.shared.u64 t, %1; cvt.u32.u64 %0, t; }"
        : "=r"(a) : "l"(p));
    return a;
}
__device__ __forceinline__ uint32_t packbf(float hi, float lo) {
    uint32_t d; asm("cvt.rn.bf16x2.f32 %0, %1, %2;" : "=r"(d) : "f"(hi), "f"(lo));
    return d;
}
__device__ __forceinline__ float hi_f(uint32_t r) { return __uint_as_float(r & 0xffff0000u); }
__device__ __forceinline__ float lo_f(uint32_t r) { return __uint_as_float(r << 16); }

__device__ __forceinline__ void mma16816(float* c,
    uint32_t a0, uint32_t a1, uint32_t a2, uint32_t a3,
    uint32_t b0, uint32_t b1)
{
    asm("mma.sync.aligned.m16n8k16.row.col.f32.bf16.bf16.f32 "
        "{%0,%1,%2,%3}, {%4,%5,%6,%7}, {%8,%9}, {%0,%1,%2,%3};"
        : "+f"(c[0]), "+f"(c[1]), "+f"(c[2]), "+f"(c[3])
        : "r"(a0), "r"(a1), "r"(a2), "r"(a3), "r"(b0), "r"(b1));
}
__device__ __forceinline__ void ldsm4(uint32_t* r, uint32_t a) {
    asm volatile("ldmatrix.sync.aligned.m8n8.x4.shared.b16 {%0,%1,%2,%3}, [%4];"
        : "=r"(r[0]), "=r"(r[1]), "=r"(r[2]), "=r"(r[3]) : "r"(a));
}
__device__ __forceinline__ void ldsm4t(uint32_t* r, uint32_t a) {
    asm volatile("ldmatrix.sync.aligned.m8n8.x4.trans.shared.b16 {%0,%1,%2,%3}, [%4];"
        : "=r"(r[0]), "=r"(r[1]), "=r"(r[2]), "=r"(r[3]) : "r"(a));
}

__global__ __launch_bounds__(NT, 3) void swa_mma17(
    const float* __restrict__ q,
    const float* __restrict__ k,
    const float* __restrict__ v,
    float* __restrict__ out)
{
    extern __shared__ char smem[];
    const uint32_t sb = smem_u32(smem);

    const int t    = threadIdx.x;
    const int lane = t & 31;
    const int wid  = t >> 5;
    const int g    = lane >> 2;
    const int tg   = lane & 3;
    const int i0   = blockIdx.x * BM;
    const int w0   = i0 + wid * 16;
    const int rowA = w0 + g;
    const int rowB = rowA + 8;
    const size_t base = (size_t)blockIdx.y * SEQ * DH;

    // chunk-invariant ldmatrix lane bases (stage 0; add (c&3)*STG)
    const uint32_t khB = sb + ((lane & 7) * KST + (lane >> 3) * 8) * 2;
    const uint32_t klB = khB + ARR;
    const uint32_t vhB = sb + 2 * ARR
                       + (((lane & 7) + ((lane >> 3) & 1) * 8) * KST) * 2
                       + (lane >> 4) * 16;
    const uint32_t vlB = vhB + ARR;

    // loader destination offsets (4 float4 per thread per array)
    uint32_t ldo[4];
    #pragma unroll
    for (int i = 0; i < 4; i++) {
        const int gi = t + i * NT;
        ldo[i] = (uint32_t)((gi >> 4) * 144 + (gi & 15) * 8);
    }

    // ---- Q fragments (hi/lo), loaded once (v7 verbatim) ----
    uint32_t qh[4][4], ql[4][4];
    {
        const float* qp = q + base;
        #pragma unroll
        for (int kd = 0; kd < 4; kd++) {
            const int d0 = kd * 16 + tg * 2;
            const float xA0 = qp[(size_t)rowA * DH + d0];
            const float xA1 = qp[(size_t)rowA * DH + d0 + 1];
            const float xB0 = qp[(size_t)rowB * DH + d0];
            const float xB1 = qp[(size_t)rowB * DH + d0 + 1];
            const float yA0 = qp[(size_t)rowA * DH + d0 + 8];
            const float yA1 = qp[(size_t)rowA * DH + d0 + 9];
            const float yB0 = qp[(size_t)rowB * DH + d0 + 8];
            const float yB1 = qp[(size_t)rowB * DH + d0 + 9];
            qh[kd][0] = packbf(xA1, xA0);
            qh[kd][1] = packbf(xB1, xB0);
            qh[kd][2] = packbf(yA1, yA0);
            qh[kd][3] = packbf(yB1, yB0);
            ql[kd][0] = packbf(xA1 - hi_f(qh[kd][0]), xA0 - lo_f(qh[kd][0]));
            ql[kd][1] = packbf(xB1 - hi_f(qh[kd][1]), xB0 - lo_f(qh[kd][1]));
            ql[kd][2] = packbf(yA1 - hi_f(qh[kd][2]), yA0 - lo_f(qh[kd][2]));
            ql[kd][3] = packbf(yB1 - hi_f(qh[kd][3]), yB0 - lo_f(qh[kd][3]));
        }
    }

    float o[8][4];
    #pragma unroll
    for (int m = 0; m < 8; m++) { o[m][0]=0.f; o[m][1]=0.f; o[m][2]=0.f; o[m][3]=0.f; }
    float lsum0 = 0.f, lsum1 = 0.f;

    int js = i0 - WIN + 1;
    if (js < 0) js = 0;
    js &= ~(BN - 1);
    const int nch = (i0 + BM - js) / BN;    // 2..10, block-uniform

    float4 kreg[4], vreg[4];

    auto stschunk = [&](int b) {
        char* rb = smem + b * STG;
        #pragma unroll
        for (int i = 0; i < 4; i++) {
            const uint32_t off = ldo[i];
            const float4 kv = kreg[i];
            uint32_t h01 = packbf(kv.y, kv.x);
            uint32_t h23 = packbf(kv.w, kv.z);
            *(uint2*)(rb + off)       = make_uint2(h01, h23);          // Kh
            *(uint2*)(rb + ARR + off) = make_uint2(
                packbf(kv.y - hi_f(h01), kv.x - lo_f(h01)),
                packbf(kv.w - hi_f(h23), kv.z - lo_f(h23)));           // Kl
            const float4 vv = vreg[i];
            h01 = packbf(vv.y, vv.x);
            h23 = packbf(vv.w, vv.z);
            *(uint2*)(rb + 2 * ARR + off) = make_uint2(h01, h23);      // Vh
            *(uint2*)(rb + 3 * ARR + off) = make_uint2(
                packbf(vv.y - hi_f(h01), vv.x - lo_f(h01)),
                packbf(vv.w - hi_f(h23), vv.z - lo_f(h23)));           // Vl
        }
    };
    auto ldgchunk = [&](int c) {
        const int j0 = js + c * BN;
        const float4* kp = (const float4*)(k + base + (size_t)j0 * DH);
        const float4* vp = (const float4*)(v + base + (size_t)j0 * DH);
        #pragma unroll
        for (int i = 0; i < 4; i++) {
            kreg[i] = kp[t + i * NT];
            vreg[i] = vp[t + i * NT];
        }
    };

    // prologue: chunks 0,1 -> stages 0,1; chunk 2 staged in regs
    ldgchunk(0);
    stschunk(0);
    if (nch > 1) { ldgchunk(1); stschunk(1); }
    if (nch > 2) ldgchunk(2);
    __syncthreads();

    for (int c = 0; c < nch; c++) {
        const int j0  = js + c * BN;
        const uint32_t bo = (uint32_t)(c & 3) * STG;

        // ---- compute from stage c&3 (v7 verbatim) ----
        if (j0 <= w0 + 15 && j0 + BN - 1 >= w0 - WIN + 1) {
            float s[4][4];
            #pragma unroll
            for (int nt = 0; nt < 4; nt++) { s[nt][0]=0.f; s[nt][1]=0.f; s[nt][2]=0.f; s[nt][3]=0.f; }

            #pragma unroll
            for (int kd2 = 0; kd2 < 2; kd2++) {
                #pragma unroll
                for (int nt = 0; nt < 4; nt++) {
                    uint32_t bh[4], bl[4];
                    const uint32_t off = bo + (uint32_t)(nt * 8 * KST * 2 + kd2 * 64);
                    ldsm4(bh, khB + off);
                    ldsm4(bl, klB + off);
                    const int k0 = 2 * kd2, k1 = 2 * kd2 + 1;
                    mma16816(s[nt], qh[k0][0], qh[k0][1], qh[k0][2], qh[k0][3], bh[0], bh[1]);
                    mma16816(s[nt], qh[k1][0], qh[k1][1], qh[k1][2], qh[k1][3], bh[2], bh[3]);
                    mma16816(s[nt], qh[k0][0], qh[k0][1], qh[k0][2], qh[k0][3], bl[0], bl[1]);
                    mma16816(s[nt], qh[k1][0], qh[k1][1], qh[k1][2], qh[k1][3], bl[2], bl[3]);
                    mma16816(s[nt], ql[k0][0], ql[k0][1], ql[k0][2], ql[k0][3], bh[0], bh[1]);
                    mma16816(s[nt], ql[k1][0], ql[k1][1], ql[k1][2], ql[k1][3], bh[2], bh[3]);
                }
            }

            #pragma unroll
            for (int nt = 0; nt < 4; nt++) {
                const int jc = j0 + nt * 8 + tg * 2;
                const float p00 = ((unsigned)(rowA - jc)       < (unsigned)WIN) ? __expf(s[nt][0]) : 0.f;
                const float p01 = ((unsigned)(rowA - (jc + 1)) < (unsigned)WIN) ? __expf(s[nt][1]) : 0.f;
                const float p10 = ((unsigned)(rowB - jc)       < (unsigned)WIN) ? __expf(s[nt][2]) : 0.f;
                const float p11 = ((unsigned)(rowB - (jc + 1)) < (unsigned)WIN) ? __expf(s[nt][3]) : 0.f;
                lsum0 += p00 + p01;
                lsum1 += p10 + p11;
                s[nt][0] = p00; s[nt][1] = p01; s[nt][2] = p10; s[nt][3] = p11;
            }

            uint32_t aH[2][4], aL[2][4];
            #pragma unroll
            for (int ks = 0; ks < 2; ks++) {
                const float* pa = s[2 * ks];
                const float* pb = s[2 * ks + 1];
                aH[ks][0] = packbf(pa[1], pa[0]);
                aH[ks][1] = packbf(pa[3], pa[2]);
                aH[ks][2] = packbf(pb[1], pb[0]);
                aH[ks][3] = packbf(pb[3], pb[2]);
                aL[ks][0] = packbf(pa[1] - hi_f(aH[ks][0]), pa[0] - lo_f(aH[ks][0]));
                aL[ks][1] = packbf(pa[3] - hi_f(aH[ks][1]), pa[2] - lo_f(aH[ks][1]));
                aL[ks][2] = packbf(pb[1] - hi_f(aH[ks][2]), pb[0] - lo_f(aH[ks][2]));
                aL[ks][3] = packbf(pb[3] - hi_f(aH[ks][3]), pb[2] - lo_f(aH[ks][3]));
            }

            #pragma unroll
            for (int ks = 0; ks < 2; ks++) {
                #pragma unroll
                for (int mt2 = 0; mt2 < 4; mt2++) {
                    uint32_t bh[4], bl[4];
                    const uint32_t off = bo + (uint32_t)(ks * 16 * KST * 2 + mt2 * 32);
                    ldsm4t(bh, vhB + off);
                    ldsm4t(bl, vlB + off);
                    const int m0 = 2 * mt2, m1 = 2 * mt2 + 1;
                    mma16816(o[m0], aH[ks][0], aH[ks][1], aH[ks][2], aH[ks][3], bh[0], bh[1]);
                    mma16816(o[m1], aH[ks][0], aH[ks][1], aH[ks][2], aH[ks][3], bh[2], bh[3]);
                    mma16816(o[m0], aH[ks][0], aH[ks][1], aH[ks][2], aH[ks][3], bl[0], bl[1]);
                    mma16816(o[m1], aH[ks][0], aH[ks][1], aH[ks][2], aH[ks][3], bl[2], bl[3]);
                    mma16816(o[m0], aL[ks][0], aL[ks][1], aL[ks][2], aL[ks][3], bh[0], bh[1]);
                    mma16816(o[m1], aL[ks][0], aL[ks][1], aL[ks][2], aL[ks][3], bh[2], bh[3]);
                }
            }
        }

        // ---- publish chunk c+2 (staged); prefetch chunk c+3 ----
        if (c + 2 < nch) {
            stschunk((c + 2) & 3);
            if (c + 3 < nch) ldgchunk(c + 3);
        }
        // barrier only every other chunk
        if (c & 1) __syncthreads();
    }

    // ---- finalize (v7 verbatim) ----
    lsum0 += __shfl_xor_sync(0xffffffffu, lsum0, 1);
    lsum0 += __shfl_xor_sync(0xffffffffu, lsum0, 2);
    lsum1 += __shfl_xor_sync(0xffffffffu, lsum1, 1);
    lsum1 += __shfl_xor_sync(0xffffffffu, lsum1, 2);
    const float ia = 1.f / lsum0;
    const float ib = 1.f / lsum1;

    float* op = out + base;
    #pragma unroll
    for (int mt = 0; mt < 8; mt++) {
        const int d0 = mt * 8 + tg * 2;
        *(float2*)&op[(size_t)rowA * DH + d0] = make_float2(o[mt][0] * ia, o[mt][1] * ia);
        *(float2*)&op[(size_t)rowB * DH + d0] = make_float2(o[mt][2] * ib, o[mt][3] * ib);
    }
}

extern "C" void kernel_launch(void* const* d_in, const int* in_sizes, int n_in,
                              void* d_out, int out_size)
{
    const float* q = (const float*)d_in[0];
    const float* k = (const float*)d_in[1];
    const float* v = (const float*)d_in[2];
    // d_in[3] = mask (analytic, unused)
    float* out = (float*)d_out;

    cudaFuncSetAttribute(swa_mma17, cudaFuncAttributeMaxDynamicSharedMemorySize, SMEM_TOTAL);

    dim3 grid(SEQ / BM, 2 * 12);   // 32 x 24 = 768 CTAs
    dim3 block(NT);
    swa_mma17<<<grid, block, SMEM_TOTAL>>>(q, k, v, out);
}